// round 4
// baseline (speedup 1.0000x reference)
#include <cuda_runtime.h>
#include <math.h>

// Problem dims
#define TT   512
#define BB   64
#define INPS 256
#define HH   512
#define KMAX 1024

// Recurrence kernel config
#define NCTA 128      // 4 cells x 32 CTAs
#define JT   16       // j rows per CTA (32 CTAs x 16 = 512)
#define KC   256      // k chunk staged in smem

// ---------------- device scratch (static: no allocation allowed) -------------
__device__ float    g_Wc[4][HH][KMAX];     // combined [W_ih(*mask) | W_hh] per cell, [j][k]
__device__ float    g_bias[4][HH];         // b_ih + b_hh
__device__ float    g_xT[TT][INPS][BB];    // x transposed to [t][i][b]
__device__ float    g_out0T[TT][HH][BB];   // layer0 outputs, [t][j][b]
__device__ float    g_out1T[TT][HH][BB];   // layer1 outputs, [t][j][b]
__device__ float    g_hT[4][2][HH][BB];    // double-buffered hidden state per cell, [j][b]
__device__ unsigned g_bar;                 // grid barrier counter (monotonic)

struct Params { const float* p[20]; };

// ---------------- init: zero states + reset barrier (every replay) ----------
__global__ void init_kernel() {
    int idx = blockIdx.x * blockDim.x + threadIdx.x;
    int stride = gridDim.x * blockDim.x;
    float* h = &g_hT[0][0][0][0];
    const int n = 4 * 2 * HH * BB;
    for (int i = idx; i < n; i += stride) h[i] = 0.0f;
    if (idx == 0) g_bar = 0u;
}

// ---------------- prep: build combined (masked) weights + biases ------------
__global__ void prep_kernel(Params P) {
    int idx = blockIdx.x * blockDim.x + threadIdx.x;
    int stride = gridDim.x * blockDim.x;

    // cell 0: [W_ih0 (H x IN) | W_hh0 (H x H)], no mask
    for (int i = idx; i < HH * INPS; i += stride) {
        int j = i / INPS, k = i - j * INPS;
        g_Wc[0][j][k] = P.p[1][i];
    }
    for (int i = idx; i < HH * HH; i += stride) {
        int j = i / HH, k = i - j * HH;
        g_Wc[0][j][INPS + k] = P.p[3][i];
    }
    // cells 1..3: masked input weights + hidden weights
    const int ihI[3]  = {5, 10, 15};
    const int mI[3]   = {6, 11, 16};
    const int hhI[3]  = {8, 13, 18};
    for (int c = 0; c < 3; ++c) {
        const float* wih = P.p[ihI[c]];
        const float* msk = P.p[mI[c]];
        const float* whh = P.p[hhI[c]];
        for (int i = idx; i < HH * HH; i += stride) {
            int j = i / HH, k = i - j * HH;
            g_Wc[c + 1][j][k]      = wih[i] * msk[i];
            g_Wc[c + 1][j][HH + k] = whh[i];
        }
    }
    // combined biases
    const int bihI[4] = {2, 7, 12, 17};
    const int bhhI[4] = {4, 9, 14, 19};
    for (int i = idx; i < 4 * HH; i += stride) {
        int c = i / HH, j = i - c * HH;
        g_bias[c][j] = P.p[bihI[c]][j] + P.p[bhhI[c]][j];
    }
}

// ---------------- transpose x: [t][b][i] -> [t][i][b] -----------------------
__global__ void transpose_x_kernel(const float* __restrict__ x) {
    int idx = blockIdx.x * blockDim.x + threadIdx.x;
    int stride = gridDim.x * blockDim.x;
    const int n = TT * BB * INPS;
    for (int e = idx; e < n; e += stride) {
        int t = e / (INPS * BB);
        int r = e - t * (INPS * BB);
        int i = r / BB, b = r - i * BB;
        g_xT[t][i][b] = x[(t * BB + b) * INPS + i];
    }
}

// ---------------- persistent pipelined recurrence ----------------------------
// Grid: 128 CTAs (cell = blockIdx>>5, j-tile = blockIdx&31). 256 threads/CTA.
// Thread map: warp w, lane l. b = (w&1)*32 + l  (covers 64 batch),
//             j's = jbase..jbase+3 with jbase = (w>>1)*4  (covers JT=16 rows).
// Smem: Ws[KMAX][JT] (weight slice, resident whole kernel) + vsm[KC][BB].
__global__ void __launch_bounds__(256, 1)
rec_kernel(float* __restrict__ dout) {
    extern __shared__ float smem[];
    float* Ws  = smem;                 // KMAX*JT floats = 64KB
    float* vsm = smem + KMAX * JT;     // KC*BB floats  = 64KB

    const int cell = blockIdx.x >> 5;
    const int j0   = (blockIdx.x & 31) * JT;
    const int tid  = threadIdx.x;
    const int w    = tid >> 5;
    const int l    = tid & 31;
    const int b    = ((w & 1) << 5) | l;
    const int jbase = (w >> 1) << 2;

    const int Kin  = (cell == 0) ? INPS : HH;
    const int Ktot = Kin + HH;

    // Load weight slice transposed into smem: Ws[k][jj] = Wc[cell][j0+jj][k]
    for (int jj = 0; jj < JT; ++jj) {
        const float* src = &g_Wc[cell][j0 + jj][0];
        for (int k = tid; k < Ktot; k += 256)
            Ws[k * JT + jj] = src[k];
    }
    const float4 bias4 = *(const float4*)&g_bias[cell][j0 + jbase];
    __syncthreads();

    const int delay = (cell == 0) ? 0 : ((cell == 2) ? 2 : 1);
    unsigned bar_target = 0;

    for (int s = 0; s < TT + 2; ++s) {
        const int t = s - delay;
        const bool active = (t >= 0) && (t < TT);
        if (active) {
            const float* vin = (cell == 0) ? &g_xT[t][0][0]
                             : (cell == 2) ? &g_out1T[t][0][0]
                                           : &g_out0T[t][0][0];
            const float* vh = &g_hT[cell][s & 1][0][0];

            float a0 = bias4.x, a1 = bias4.y, a2 = bias4.z, a3 = bias4.w;

            const int nchunk = Ktot / KC;   // 3 (cell0) or 4
            for (int c = 0; c < nchunk; ++c) {
                const int k0 = c * KC;
                // stage KC x BB activation slice into smem (coalesced, L2-only)
                const float* src = (k0 < Kin) ? (vin + k0 * BB)
                                              : (vh + (k0 - Kin) * BB);
                const float4* s4 = (const float4*)src;
                float4* d4 = (float4*)vsm;
                #pragma unroll
                for (int i = 0; i < (KC * BB / 4) / 256; ++i)
                    d4[i * 256 + tid] = __ldcg(&s4[i * 256 + tid]);
                __syncthreads();

                const float* wp = &Ws[k0 * JT + jbase];
                #pragma unroll 8
                for (int kk = 0; kk < KC; ++kk) {
                    const float v = vsm[kk * BB + b];
                    const float4 wv = *(const float4*)&wp[kk * JT];
                    a0 += wv.x * v;
                    a1 += wv.y * v;
                    a2 += wv.z * v;
                    a3 += wv.w * v;
                }
                __syncthreads();
            }

            a0 = tanhf(a0); a1 = tanhf(a1); a2 = tanhf(a2); a3 = tanhf(a3);

            // write new hidden state (parity flip)
            float* hw = &g_hT[cell][(s + 1) & 1][j0 + jbase][b];
            hw[0 * BB] = a0; hw[1 * BB] = a1; hw[2 * BB] = a2; hw[3 * BB] = a3;

            if (cell == 0) {
                float* o = &g_out0T[t][j0 + jbase][b];
                o[0 * BB] = a0; o[1 * BB] = a1; o[2 * BB] = a2; o[3 * BB] = a3;
            } else if (cell == 1) {
                float* o = &g_out1T[t][j0 + jbase][b];
                o[0 * BB] = a0; o[1 * BB] = a1; o[2 * BB] = a2; o[3 * BB] = a3;
            } else if (cell == 2 && t == TT - 1) {
                // final output: layer2 + skip (skip final state is in buf[s&1])
                const float* hs = &g_hT[3][s & 1][j0 + jbase][b];
                float4 r;
                r.x = a0 + __ldcg(&hs[0 * BB]);
                r.y = a1 + __ldcg(&hs[1 * BB]);
                r.z = a2 + __ldcg(&hs[2 * BB]);
                r.w = a3 + __ldcg(&hs[3 * BB]);
                *(float4*)&dout[b * HH + j0 + jbase] = r;
            }
        }

        // ---- grid barrier (all 128 CTAs, active or not) ----
        __threadfence();
        __syncthreads();
        if (tid == 0) {
            atomicAdd(&g_bar, 1u);
            bar_target += NCTA;
            while (*(volatile unsigned*)&g_bar < bar_target) { }
            __threadfence();
        }
        __syncthreads();
    }
}

// ---------------- launch ------------------------------------------------------
extern "C" void kernel_launch(void* const* d_in, const int* in_sizes, int n_in,
                              void* d_out, int out_size) {
    (void)in_sizes; (void)n_in; (void)out_size;

    Params P;
    for (int i = 0; i < 20; ++i) P.p[i] = (const float*)d_in[i];

    // 128KB dynamic smem for the recurrence kernel (idempotent, capture-safe)
    static_assert(KMAX * JT * 4 + KC * BB * 4 == 131072, "smem size");
    cudaFuncSetAttribute(rec_kernel,
                         cudaFuncAttributeMaxDynamicSharedMemorySize, 131072);

    init_kernel<<<128, 256>>>();
    prep_kernel<<<512, 256>>>(P);
    transpose_x_kernel<<<512, 256>>>((const float*)d_in[0]);
    rec_kernel<<<NCTA, 256, 131072>>>((float*)d_out);
}

// round 5
// speedup vs baseline: 1.9911x; 1.9911x over previous
#include <cuda_runtime.h>
#include <cuda_bf16.h>
#include <math.h>
#include <stdint.h>

// Problem dims
#define TT   512
#define BB   64
#define INPS 256
#define HH   512

// Kernel config
#define NCTA 128      // 4 cells x 32 j-tiles
#define JT   16
#define KC   256      // k rows per staged chunk

// Smem layout
#define SMEM_W_BYTES 65536                 // 64 kc * 2 (hi/lo) * 512B ldmatrix tiles
#define VROW_B16     72                    // padded row stride (bf16 elems) -> 144B
#define VPLANE_BYTES (KC * VROW_B16 * 2)   // 36864
#define VBUF_BYTES   (2 * VPLANE_BYTES)    // 73728 (hi+lo planes)
#define SMEM_TOTAL   (SMEM_W_BYTES + 2 * VBUF_BYTES)  // 212992

// ---------------- device scratch ---------------------------------------------
// Weights pre-split + pre-tiled for ldmatrix: [cell][jtile][kc][hl][tile*64+row*8+col]
__device__ uint16_t g_WA[4][32][64][2][256];
__device__ float    g_bias[4][HH];
__device__ uint16_t g_x2[2][TT][INPS][BB];        // x as bf16 hi/lo planes, [p][t][i][b]
__device__ uint16_t g_h2[4][2][2][HH][BB];        // state: [cell][parity][plane][j][b]
__device__ unsigned g_bar;

struct Params { const float* p[20]; };

// ---------------- helpers -----------------------------------------------------
__device__ __forceinline__ uint32_t s2u(const void* p) {
    uint32_t a;
    asm("{ .reg .u64 t; cvta.to.shared.u64 t, %1; cvt.u32.u64 %0, t; }"
        : "=r"(a) : "l"(p));
    return a;
}

__device__ __forceinline__ void ldsm_x4(uint32_t& r0, uint32_t& r1,
                                        uint32_t& r2, uint32_t& r3, uint32_t addr) {
    asm volatile("ldmatrix.sync.aligned.m8n8.x4.shared.b16 {%0,%1,%2,%3}, [%4];"
                 : "=r"(r0), "=r"(r1), "=r"(r2), "=r"(r3) : "r"(addr));
}

__device__ __forceinline__ void ldsm_x2t(uint32_t& r0, uint32_t& r1, uint32_t addr) {
    asm volatile("ldmatrix.sync.aligned.m8n8.x2.trans.shared.b16 {%0,%1}, [%2];"
                 : "=r"(r0), "=r"(r1) : "r"(addr));
}

__device__ __forceinline__ void mma_bf16(float* c,
                                         uint32_t a0, uint32_t a1, uint32_t a2, uint32_t a3,
                                         uint32_t b0, uint32_t b1) {
    asm volatile("mma.sync.aligned.m16n8k16.row.col.f32.bf16.bf16.f32 "
                 "{%0,%1,%2,%3}, {%4,%5,%6,%7}, {%8,%9}, {%0,%1,%2,%3};"
                 : "+f"(c[0]), "+f"(c[1]), "+f"(c[2]), "+f"(c[3])
                 : "r"(a0), "r"(a1), "r"(a2), "r"(a3), "r"(b0), "r"(b1));
}

__device__ __forceinline__ uint32_t pack_split(float x, float y, uint32_t& lopack) {
    __nv_bfloat16 hx = __float2bfloat16(x), hy = __float2bfloat16(y);
    __nv_bfloat16 lx = __float2bfloat16(x - __bfloat162float(hx));
    __nv_bfloat16 ly = __float2bfloat16(y - __bfloat162float(hy));
    lopack = (uint32_t)__bfloat16_as_ushort(lx) | ((uint32_t)__bfloat16_as_ushort(ly) << 16);
    return (uint32_t)__bfloat16_as_ushort(hx) | ((uint32_t)__bfloat16_as_ushort(hy) << 16);
}

// ---------------- init: zero states + reset barrier --------------------------
__global__ void init_kernel() {
    int idx = blockIdx.x * blockDim.x + threadIdx.x;
    int stride = gridDim.x * blockDim.x;
    uint32_t* h = (uint32_t*)&g_h2[0][0][0][0][0];
    const int n = (int)(sizeof(g_h2) / 4);
    for (int i = idx; i < n; i += stride) h[i] = 0u;
    if (idx == 0) g_bar = 0u;
}

// ---------------- prep: split + tile weights, combine biases ------------------
__device__ __forceinline__ void put_w(int c, int j, int k, float w) {
    int jt = j >> 4, jl = j & 15, kc = k >> 4, kk = k & 15;
    int t = (jl >> 3) | ((kk >> 3) << 1);
    int off = t * 64 + (jl & 7) * 8 + (kk & 7);
    __nv_bfloat16 hi = __float2bfloat16(w);
    __nv_bfloat16 lo = __float2bfloat16(w - __bfloat162float(hi));
    g_WA[c][jt][kc][0][off] = __bfloat16_as_ushort(hi);
    g_WA[c][jt][kc][1][off] = __bfloat16_as_ushort(lo);
}

__global__ void prep_kernel(Params P) {
    int idx = blockIdx.x * blockDim.x + threadIdx.x;
    int stride = gridDim.x * blockDim.x;

    // cell 0: [W_ih0 (H x IN) | W_hh0 (H x H)]
    for (int i = idx; i < HH * INPS; i += stride) {
        int j = i / INPS, k = i - j * INPS;
        put_w(0, j, k, P.p[1][i]);
    }
    for (int i = idx; i < HH * HH; i += stride) {
        int j = i / HH, k = i - j * HH;
        put_w(0, j, INPS + k, P.p[3][i]);
    }
    const int ihI[3] = {5, 10, 15};
    const int mI[3]  = {6, 11, 16};
    const int hhI[3] = {8, 13, 18};
    for (int c = 0; c < 3; ++c) {
        const float* wih = P.p[ihI[c]];
        const float* msk = P.p[mI[c]];
        const float* whh = P.p[hhI[c]];
        for (int i = idx; i < HH * HH; i += stride) {
            int j = i / HH, k = i - j * HH;
            put_w(c + 1, j, k, wih[i] * msk[i]);
            put_w(c + 1, j, HH + k, whh[i]);
        }
    }
    const int bihI[4] = {2, 7, 12, 17};
    const int bhhI[4] = {4, 9, 14, 19};
    for (int i = idx; i < 4 * HH; i += stride) {
        int c = i / HH, j = i - c * HH;
        g_bias[c][j] = P.p[bihI[c]][j] + P.p[bhhI[c]][j];
    }
}

// ---------------- x convert: [t][b][i] fp32 -> hi/lo planes [p][t][i][b] -----
__global__ void xconv_kernel(const float* __restrict__ x) {
    int idx = blockIdx.x * blockDim.x + threadIdx.x;
    int stride = gridDim.x * blockDim.x;
    const int n = TT * INPS * BB;
    for (int e = idx; e < n; e += stride) {
        int t = e / (INPS * BB);
        int r = e - t * (INPS * BB);
        int i = r / BB, b = r - i * BB;
        float f = x[(t * BB + b) * INPS + i];
        __nv_bfloat16 hi = __float2bfloat16(f);
        __nv_bfloat16 lo = __float2bfloat16(f - __bfloat162float(hi));
        g_x2[0][t][i][b] = __bfloat16_as_ushort(hi);
        g_x2[1][t][i][b] = __bfloat16_as_ushort(lo);
    }
}

// ---------------- chunk source pointers --------------------------------------
__device__ __forceinline__ void chunk_ptrs(int cell, int c, int t, int par,
                                           int srccell, const int4* pl[2]) {
#pragma unroll
    for (int p = 0; p < 2; ++p) {
        const uint16_t* b;
        if (cell == 0) {
            b = (c == 0) ? &g_x2[p][t][0][0]
                         : &g_h2[0][par][p][(c - 1) * KC][0];
        } else {
            b = (c < 2) ? &g_h2[srccell][par][p][c * KC][0]
                        : &g_h2[cell][par][p][(c - 2) * KC][0];
        }
        pl[p] = (const int4*)b;
    }
}

// ---------------- persistent pipelined recurrence (tensor-core) ---------------
// 128 CTAs: cell = bid>>5, j-tile = bid&31. 256 threads = 8 warps; warp w owns
// batch slice b in [w*8, w*8+8). Each warp computes the full 16(j) x 8(b) tile.
__global__ void __launch_bounds__(256, 1)
rec_kernel(float* __restrict__ dout) {
    extern __shared__ char smem[];
    const uint32_t smem_u = s2u(smem);
    const uint32_t wsm_u  = smem_u;
    const uint32_t vsm_u  = smem_u + SMEM_W_BYTES;

    const int cell  = blockIdx.x >> 5;
    const int jtile = blockIdx.x & 31;
    const int j0    = jtile * JT;
    const int tid   = threadIdx.x;
    const int w     = tid >> 5;
    const int lane  = tid & 31;
    const int g     = lane >> 2;
    const int tig   = lane & 3;
    const int bw    = w * 8;

    const int Ktot   = (cell == 0) ? (INPS + HH) : (2 * HH);
    const int nchunk = Ktot / KC;       // 3 or 4

    // weights -> smem (ldmatrix-ready)
    {
        const int4* src = (const int4*)&g_WA[cell][jtile][0][0][0];
        int4* dst = (int4*)smem;
        const int n4 = (Ktot / 16) * 1024 / 16;   // kc * 1KB / 16B
        for (int i = tid; i < n4; i += 256) dst[i] = src[i];
    }
    const float bias_g  = g_bias[cell][j0 + g];
    const float bias_g8 = g_bias[cell][j0 + g + 8];
    __syncthreads();

    // per-lane invariant pieces of ldmatrix addresses
    const uint32_t a_lane = wsm_u + ((uint32_t)(lane >> 3) << 7) + ((uint32_t)(lane & 7) << 4);
    const uint32_t b_lane = (uint32_t)((lane & 15) * 144 + bw * 2);

    const int delay   = (cell == 0) ? 0 : ((cell == 2) ? 2 : 1);
    const int srccell = (cell == 2) ? 1 : 0;
    unsigned bar_target = 0;

    for (int s = 0; s < TT + 2; ++s) {
        const int t = s - delay;
        const bool active = (t >= 0) && (t < TT);
        if (active) {
            const int par = s & 1;
            const int4* pl[2];
            int4 r[16];

            // prefetch chunk 0
            chunk_ptrs(cell, 0, t, par, srccell, pl);
#pragma unroll
            for (int i = 0; i < 16; ++i) {
                int p = i >> 3, e = ((i & 7) << 8) + tid;
                r[i] = __ldcg(pl[p] + e);
            }

            float accA[4] = {bias_g, bias_g, bias_g8, bias_g8};
            float accB[4] = {0.f, 0.f, 0.f, 0.f};
            float accC[4] = {0.f, 0.f, 0.f, 0.f};

            int buf = 0;
            for (int c = 0; c < nchunk; ++c) {
                // store staged regs to smem buffer
                char* vptr = smem + SMEM_W_BYTES + buf * VBUF_BYTES;
#pragma unroll
                for (int i = 0; i < 16; ++i) {
                    int p = i >> 3, e = ((i & 7) << 8) + tid;
                    *(int4*)(vptr + p * VPLANE_BYTES + (e >> 3) * 144 + (e & 7) * 16) = r[i];
                }
                __syncthreads();

                // issue prefetch for next chunk (overlaps with MMAs below)
                if (c + 1 < nchunk) {
                    chunk_ptrs(cell, c + 1, t, par, srccell, pl);
#pragma unroll
                    for (int i = 0; i < 16; ++i) {
                        int p = i >> 3, e = ((i & 7) << 8) + tid;
                        r[i] = __ldcg(pl[p] + e);
                    }
                }

                const uint32_t vb = vsm_u + buf * VBUF_BYTES + b_lane;
#pragma unroll 4
                for (int kcl = 0; kcl < 16; ++kcl) {
                    const int kcg = c * 16 + kcl;
                    const uint32_t aw = a_lane + (uint32_t)kcg * 1024u;
                    const uint32_t bv = vb + (uint32_t)kcl * 2304u;
                    uint32_t ah0, ah1, ah2, ah3, al0, al1, al2, al3;
                    uint32_t bh0, bh1, bl0, bl1;
                    ldsm_x4(ah0, ah1, ah2, ah3, aw);
                    ldsm_x4(al0, al1, al2, al3, aw + 512u);
                    ldsm_x2t(bh0, bh1, bv);
                    ldsm_x2t(bl0, bl1, bv + VPLANE_BYTES);
                    mma_bf16(accA, ah0, ah1, ah2, ah3, bh0, bh1);  // whi*vhi
                    mma_bf16(accB, ah0, ah1, ah2, ah3, bl0, bl1);  // whi*vlo
                    mma_bf16(accC, al0, al1, al2, al3, bh0, bh1);  // wlo*vhi
                }
                buf ^= 1;
            }

            // epilogue: sum splits, tanh, write split state
            float o0 = tanhf(accA[0] + accB[0] + accC[0]);   // j0+g,   b=bw+2*tig
            float o1 = tanhf(accA[1] + accB[1] + accC[1]);   // j0+g,   b+1
            float o2 = tanhf(accA[2] + accB[2] + accC[2]);   // j0+g+8, b
            float o3 = tanhf(accA[3] + accB[3] + accC[3]);   // j0+g+8, b+1
            const int np = (s + 1) & 1;
            const int b0 = bw + 2 * tig;
            uint32_t lo0, lo1;
            uint32_t hi0 = pack_split(o0, o1, lo0);
            uint32_t hi1 = pack_split(o2, o3, lo1);
            *(uint32_t*)&g_h2[cell][np][0][j0 + g][b0]     = hi0;
            *(uint32_t*)&g_h2[cell][np][1][j0 + g][b0]     = lo0;
            *(uint32_t*)&g_h2[cell][np][0][j0 + g + 8][b0] = hi1;
            *(uint32_t*)&g_h2[cell][np][1][j0 + g + 8][b0] = lo1;

            if (cell == 2 && t == TT - 1) {
                // final output: layer2 + skip (skip final state is at parity s&1)
                const unsigned short* shp = &g_h2[3][par][0][0][0];
                const unsigned short* slp = &g_h2[3][par][1][0][0];
#pragma unroll
                for (int q = 0; q < 4; ++q) {
                    const int j = j0 + g + ((q >> 1) << 3);
                    const int b = b0 + (q & 1);
                    const float ov = (q == 0) ? o0 : (q == 1) ? o1 : (q == 2) ? o2 : o3;
                    float skip = __bfloat162float(__ushort_as_bfloat16(__ldcg(&shp[j * BB + b])))
                               + __bfloat162float(__ushort_as_bfloat16(__ldcg(&slp[j * BB + b])));
                    dout[b * HH + j] = ov + skip;
                }
            }
        }

        // ---- grid barrier (all 128 CTAs) ----
        __threadfence();
        __syncthreads();
        if (tid == 0) {
            atomicAdd(&g_bar, 1u);
            bar_target += NCTA;
            while (*(volatile unsigned*)&g_bar < bar_target) { }
            __threadfence();
        }
        __syncthreads();
    }
}

// ---------------- launch ------------------------------------------------------
extern "C" void kernel_launch(void* const* d_in, const int* in_sizes, int n_in,
                              void* d_out, int out_size) {
    (void)in_sizes; (void)n_in; (void)out_size;

    Params P;
    for (int i = 0; i < 20; ++i) P.p[i] = (const float*)d_in[i];

    cudaFuncSetAttribute(rec_kernel,
                         cudaFuncAttributeMaxDynamicSharedMemorySize, SMEM_TOTAL);

    init_kernel<<<128, 256>>>();
    prep_kernel<<<512, 256>>>(P);
    xconv_kernel<<<512, 256>>>((const float*)d_in[0]);
    rec_kernel<<<NCTA, 256, SMEM_TOTAL>>>((float*)d_out);
}

// round 6
// speedup vs baseline: 2.3107x; 1.1605x over previous
#include <cuda_runtime.h>
#include <cuda_bf16.h>
#include <math.h>
#include <stdint.h>

// Problem dims
#define TT   512
#define BB   64
#define INPS 256
#define HH   512

// Kernel config
#define NCTA 128      // 4 cells x 32 j-tiles
#define JT   16
#define KC   256      // K rows staged per chunk

// Smem layout
#define VROWB        144                    // staged k-row stride (128B data + 16B pad)
#define VPLANE_BYTES (KC * VROWB)           // 36864
#define VBUF_BYTES   (2 * VPLANE_BYTES)     // 73728 (hi+lo planes)
#define RS           68                     // reduction row stride (floats)
#define RED_BYTES    (8 * JT * RS * 4)      // 34816
#define SMEM_TOTAL   (2 * VBUF_BYTES + RED_BYTES)   // 182272

// ---------------- device scratch ---------------------------------------------
// Weights pre-split + pre-tiled for ldmatrix: [cell][jtile][kc][hl][tile*64+row*8+col]
__device__ __align__(256) uint16_t g_WA[4][32][64][2][256];
__device__ __align__(256) float    g_bias[4][HH];
__device__ __align__(256) uint16_t g_x2[2][TT][INPS][BB];   // x bf16 hi/lo planes [p][t][i][b]
__device__ __align__(256) uint16_t g_h2[4][2][2][HH][BB];   // state [cell][parity][plane][j][b]
__device__ unsigned g_bar;

struct Params { const float* p[20]; };

// ---------------- helpers -----------------------------------------------------
__device__ __forceinline__ uint32_t s2u(const void* p) {
    uint32_t a;
    asm("{ .reg .u64 t; cvta.to.shared.u64 t, %1; cvt.u32.u64 %0, t; }"
        : "=r"(a) : "l"(p));
    return a;
}

__device__ __forceinline__ void ldsm_x4(uint32_t& r0, uint32_t& r1,
                                        uint32_t& r2, uint32_t& r3, uint32_t addr) {
    asm volatile("ldmatrix.sync.aligned.m8n8.x4.shared.b16 {%0,%1,%2,%3}, [%4];"
                 : "=r"(r0), "=r"(r1), "=r"(r2), "=r"(r3) : "r"(addr));
}

__device__ __forceinline__ void ldsm_x4t(uint32_t& r0, uint32_t& r1,
                                         uint32_t& r2, uint32_t& r3, uint32_t addr) {
    asm volatile("ldmatrix.sync.aligned.m8n8.x4.trans.shared.b16 {%0,%1,%2,%3}, [%4];"
                 : "=r"(r0), "=r"(r1), "=r"(r2), "=r"(r3) : "r"(addr));
}

__device__ __forceinline__ void mma_bf16(float* c,
                                         uint32_t a0, uint32_t a1, uint32_t a2, uint32_t a3,
                                         uint32_t b0, uint32_t b1) {
    asm volatile("mma.sync.aligned.m16n8k16.row.col.f32.bf16.bf16.f32 "
                 "{%0,%1,%2,%3}, {%4,%5,%6,%7}, {%8,%9}, {%0,%1,%2,%3};"
                 : "+f"(c[0]), "+f"(c[1]), "+f"(c[2]), "+f"(c[3])
                 : "r"(a0), "r"(a1), "r"(a2), "r"(a3), "r"(b0), "r"(b1));
}

__device__ __forceinline__ void cp_async16(uint32_t dst, const void* src) {
    asm volatile("cp.async.cg.shared.global [%0], [%1], 16;" :: "r"(dst), "l"(src));
}
__device__ __forceinline__ void cp_commit() { asm volatile("cp.async.commit_group;"); }
__device__ __forceinline__ void cp_wait0()  { asm volatile("cp.async.wait_group 0;" ::: "memory"); }

__device__ __forceinline__ uint32_t pack_split(float x, float y, uint32_t& lopack) {
    __nv_bfloat16 hx = __float2bfloat16(x), hy = __float2bfloat16(y);
    __nv_bfloat16 lx = __float2bfloat16(x - __bfloat162float(hx));
    __nv_bfloat16 ly = __float2bfloat16(y - __bfloat162float(hy));
    lopack = (uint32_t)__bfloat16_as_ushort(lx) | ((uint32_t)__bfloat16_as_ushort(ly) << 16);
    return (uint32_t)__bfloat16_as_ushort(hx) | ((uint32_t)__bfloat16_as_ushort(hy) << 16);
}

// ---------------- init: zero states + reset barrier --------------------------
__global__ void init_kernel() {
    int idx = blockIdx.x * blockDim.x + threadIdx.x;
    int stride = gridDim.x * blockDim.x;
    uint32_t* h = (uint32_t*)&g_h2[0][0][0][0][0];
    const int n = (int)(sizeof(g_h2) / 4);
    for (int i = idx; i < n; i += stride) h[i] = 0u;
    if (idx == 0) g_bar = 0u;
}

// ---------------- prep: split + tile weights, combine biases ------------------
__device__ __forceinline__ void put_w(int c, int j, int k, float w) {
    int jt = j >> 4, jl = j & 15, kc = k >> 4, kk = k & 15;
    int t = (jl >> 3) | ((kk >> 3) << 1);
    int off = t * 64 + (jl & 7) * 8 + (kk & 7);
    __nv_bfloat16 hi = __float2bfloat16(w);
    __nv_bfloat16 lo = __float2bfloat16(w - __bfloat162float(hi));
    g_WA[c][jt][kc][0][off] = __bfloat16_as_ushort(hi);
    g_WA[c][jt][kc][1][off] = __bfloat16_as_ushort(lo);
}

__global__ void prep_kernel(Params P) {
    int idx = blockIdx.x * blockDim.x + threadIdx.x;
    int stride = gridDim.x * blockDim.x;

    for (int i = idx; i < HH * INPS; i += stride) {
        int j = i / INPS, k = i - j * INPS;
        put_w(0, j, k, P.p[1][i]);
    }
    for (int i = idx; i < HH * HH; i += stride) {
        int j = i / HH, k = i - j * HH;
        put_w(0, j, INPS + k, P.p[3][i]);
    }
    const int ihI[3] = {5, 10, 15};
    const int mI[3]  = {6, 11, 16};
    const int hhI[3] = {8, 13, 18};
    for (int c = 0; c < 3; ++c) {
        const float* wih = P.p[ihI[c]];
        const float* msk = P.p[mI[c]];
        const float* whh = P.p[hhI[c]];
        for (int i = idx; i < HH * HH; i += stride) {
            int j = i / HH, k = i - j * HH;
            put_w(c + 1, j, k, wih[i] * msk[i]);
            put_w(c + 1, j, HH + k, whh[i]);
        }
    }
    const int bihI[4] = {2, 7, 12, 17};
    const int bhhI[4] = {4, 9, 14, 19};
    for (int i = idx; i < 4 * HH; i += stride) {
        int c = i / HH, j = i - c * HH;
        g_bias[c][j] = P.p[bihI[c]][j] + P.p[bhhI[c]][j];
    }
}

// ---------------- x convert: [t][b][i] fp32 -> hi/lo planes [p][t][i][b] -----
__global__ void xconv_kernel(const float* __restrict__ x) {
    int idx = blockIdx.x * blockDim.x + threadIdx.x;
    int stride = gridDim.x * blockDim.x;
    const int n = TT * INPS * BB;
    for (int e = idx; e < n; e += stride) {
        int t = e / (INPS * BB);
        int r = e - t * (INPS * BB);
        int i = r / BB, b = r - i * BB;
        float f = x[(t * BB + b) * INPS + i];
        __nv_bfloat16 hi = __float2bfloat16(f);
        __nv_bfloat16 lo = __float2bfloat16(f - __bfloat162float(hi));
        g_x2[0][t][i][b] = __bfloat16_as_ushort(hi);
        g_x2[1][t][i][b] = __bfloat16_as_ushort(lo);
    }
}

// ---------------- chunk staging via cp.async ---------------------------------
__device__ __forceinline__ void issue_chunk(uint32_t vdst, int cell, int c, int t,
                                            int par, int srccell, int tid) {
    const uint16_t* src[2];
#pragma unroll
    for (int p = 0; p < 2; ++p) {
        if (cell == 0)
            src[p] = (c == 0) ? &g_x2[p][t][0][0]
                              : &g_h2[0][par][p][(c - 1) * KC][0];
        else
            src[p] = (c < 2) ? &g_h2[srccell][par][p][c * KC][0]
                             : &g_h2[cell][par][p][(c - 2) * KC][0];
    }
#pragma unroll
    for (int p = 0; p < 2; ++p) {
        const char* s = (const char*)src[p];
        const uint32_t d = vdst + p * VPLANE_BYTES;
#pragma unroll
        for (int i = 0; i < 8; ++i) {
            const int e = i * 256 + tid;            // 0..2047: (row=e>>3, seg=e&7)
            cp_async16(d + (uint32_t)(e >> 3) * (uint32_t)VROWB + (uint32_t)(e & 7) * 16u,
                       s + (size_t)e * 16);
        }
    }
}

// ---------------- persistent pipelined recurrence (K-split warps) -------------
// 128 CTAs: cell = bid>>5, j-tile = bid&31. 8 warps; warp w owns kc slice
// {c*16 + 2w, c*16 + 2w + 1 : c in chunks}; A-frags live in registers for the
// whole kernel. Cross-warp K-reduction through smem per step.
__global__ void __launch_bounds__(256, 1)
rec_kernel(float* __restrict__ dout) {
    extern __shared__ char smem[];
    const uint32_t smem_u = s2u(smem);
    const uint32_t vsm_u  = smem_u;
    float* redf = (float*)(smem + 2 * VBUF_BYTES);

    const int cell  = blockIdx.x >> 5;
    const int jtile = blockIdx.x & 31;
    const int j0    = jtile * JT;
    const int tid   = threadIdx.x;
    const int w     = tid >> 5;
    const int lane  = tid & 31;
    const int g     = lane >> 2;
    const int tig   = lane & 3;

    const int Ktot   = (cell == 0) ? (INPS + HH) : (2 * HH);
    const int nchunk = Ktot / KC;          // 3 or 4
    const int nkc    = Ktot / 16;

    // ---- load persistent A-fragments (hi+lo) into registers ----
    uint32_t A[64];
    {
        const int4* srcw = (const int4*)&g_WA[cell][jtile][0][0][0];
        int4* dstw = (int4*)smem;
        const int n4 = nkc * 1024 / 16;
        for (int i = tid; i < n4; i += 256) dstw[i] = srcw[i];
        __syncthreads();
        const uint32_t a_lane = smem_u + ((uint32_t)(lane >> 3) << 7)
                                       + ((uint32_t)(lane & 7) << 4);
#pragma unroll
        for (int c = 0; c < 4; ++c) {
            if (c < nchunk) {
#pragma unroll
                for (int i = 0; i < 2; ++i) {
                    const int kcg = c * 16 + w * 2 + i;
                    const uint32_t aw = a_lane + (uint32_t)kcg * 1024u;
                    const int ai = (c * 2 + i) * 8;
                    ldsm_x4(A[ai + 0], A[ai + 1], A[ai + 2], A[ai + 3], aw);
                    ldsm_x4(A[ai + 4], A[ai + 5], A[ai + 6], A[ai + 7], aw + 512u);
                }
            }
        }
        __syncthreads();
    }

    const int jj = tid >> 4;               // epilogue ownership: (jj, b0..b0+3)
    const int b0 = (tid & 15) * 4;
    const float bias_j = g_bias[cell][j0 + jj];

    // per-lane invariant part of B ldsm address: row (lane&15), +8 b for hi lanes
    const uint32_t b_lane = (uint32_t)(lane & 15) * (uint32_t)VROWB
                          + ((uint32_t)(lane >> 4) << 4);

    const int delay   = (cell == 0) ? 0 : ((cell == 2) ? 2 : 1);
    const int srccell = (cell == 2) ? 1 : 0;
    unsigned bar_target = 0;

    for (int s = 0; s < TT + 2; ++s) {
        const int t = s - delay;
        const bool active = (t >= 0) && (t < TT);
        if (active) {
            const int par = s & 1;

            float acc[8][4];
#pragma unroll
            for (int i = 0; i < 8; ++i) {
                acc[i][0] = 0.f; acc[i][1] = 0.f; acc[i][2] = 0.f; acc[i][3] = 0.f;
            }

            issue_chunk(vsm_u, cell, 0, t, par, srccell, tid);
            cp_commit();

            int buf = 0;
#pragma unroll
            for (int c = 0; c < 4; ++c) {
                if (c < nchunk) {
                    cp_wait0();
                    __syncthreads();
                    if (c + 1 < nchunk) {
                        issue_chunk(vsm_u + (buf ^ 1) * VBUF_BYTES,
                                    cell, c + 1, t, par, srccell, tid);
                        cp_commit();
                    }
                    const uint32_t vb = vsm_u + buf * VBUF_BYTES + b_lane;
#pragma unroll
                    for (int i = 0; i < 2; ++i) {
                        const uint32_t kb = vb + (uint32_t)((w * 2 + i) * 16) * (uint32_t)VROWB;
                        const uint32_t* ah = &A[(c * 2 + i) * 8];
#pragma unroll
                        for (int bt2 = 0; bt2 < 4; ++bt2) {
                            uint32_t bh0, bh1, bh2, bh3, bl0, bl1, bl2, bl3;
                            ldsm_x4t(bh0, bh1, bh2, bh3, kb + (uint32_t)bt2 * 32u);
                            ldsm_x4t(bl0, bl1, bl2, bl3,
                                     kb + (uint32_t)bt2 * 32u + VPLANE_BYTES);
                            mma_bf16(acc[bt2 * 2],     ah[0], ah[1], ah[2], ah[3], bh0, bh1);
                            mma_bf16(acc[bt2 * 2 + 1], ah[0], ah[1], ah[2], ah[3], bh2, bh3);
                            mma_bf16(acc[bt2 * 2],     ah[0], ah[1], ah[2], ah[3], bl0, bl1);
                            mma_bf16(acc[bt2 * 2 + 1], ah[0], ah[1], ah[2], ah[3], bl2, bl3);
                            mma_bf16(acc[bt2 * 2],     ah[4], ah[5], ah[6], ah[7], bh0, bh1);
                            mma_bf16(acc[bt2 * 2 + 1], ah[4], ah[5], ah[6], ah[7], bh2, bh3);
                        }
                    }
                    buf ^= 1;
                }
            }

            // ---- cross-warp K reduction ----
            {
                float* rw = redf + w * (JT * RS);
#pragma unroll
                for (int bt = 0; bt < 8; ++bt) {
                    const int b = bt * 8 + tig * 2;
                    *(float2*)&rw[g * RS + b]       = make_float2(acc[bt][0], acc[bt][1]);
                    *(float2*)&rw[(g + 8) * RS + b] = make_float2(acc[bt][2], acc[bt][3]);
                }
            }
            __syncthreads();

            float4 sum = make_float4(bias_j, bias_j, bias_j, bias_j);
#pragma unroll
            for (int ww = 0; ww < 8; ++ww) {
                float4 v = *(const float4*)&redf[ww * (JT * RS) + jj * RS + b0];
                sum.x += v.x; sum.y += v.y; sum.z += v.z; sum.w += v.w;
            }
            const float o0 = tanhf(sum.x), o1 = tanhf(sum.y);
            const float o2 = tanhf(sum.z), o3 = tanhf(sum.w);

            const int np = (s + 1) & 1;
            uint32_t lo0, lo1;
            const uint32_t hi0 = pack_split(o0, o1, lo0);
            const uint32_t hi1 = pack_split(o2, o3, lo1);
            *(uint2*)&g_h2[cell][np][0][j0 + jj][b0] = make_uint2(hi0, hi1);
            *(uint2*)&g_h2[cell][np][1][j0 + jj][b0] = make_uint2(lo0, lo1);

            if (cell == 2 && t == TT - 1) {
                const uint16_t* shp = &g_h2[3][par][0][j0 + jj][b0];
                const uint16_t* slp = &g_h2[3][par][1][j0 + jj][b0];
#pragma unroll
                for (int q = 0; q < 4; ++q) {
                    float skip = __bfloat162float(__ushort_as_bfloat16(__ldcg(&shp[q])))
                               + __bfloat162float(__ushort_as_bfloat16(__ldcg(&slp[q])));
                    const float ov = (q == 0) ? o0 : (q == 1) ? o1 : (q == 2) ? o2 : o3;
                    dout[(b0 + q) * HH + j0 + jj] = ov + skip;
                }
            }
        }

        // ---- grid barrier (all 128 CTAs) ----
        __threadfence();
        __syncthreads();
        if (tid == 0) {
            atomicAdd(&g_bar, 1u);
            bar_target += NCTA;
            while (*(volatile unsigned*)&g_bar < bar_target) { }
            __threadfence();
        }
        __syncthreads();
    }
}

// ---------------- launch ------------------------------------------------------
extern "C" void kernel_launch(void* const* d_in, const int* in_sizes, int n_in,
                              void* d_out, int out_size) {
    (void)in_sizes; (void)n_in; (void)out_size;

    Params P;
    for (int i = 0; i < 20; ++i) P.p[i] = (const float*)d_in[i];

    cudaFuncSetAttribute(rec_kernel,
                         cudaFuncAttributeMaxDynamicSharedMemorySize, SMEM_TOTAL);

    init_kernel<<<128, 256>>>();
    prep_kernel<<<512, 256>>>(P);
    xconv_kernel<<<512, 256>>>((const float*)d_in[0]);
    rec_kernel<<<NCTA, 256, SMEM_TOTAL>>>((float*)d_out);
}

// round 7
// speedup vs baseline: 3.0998x; 1.3415x over previous
#include <cuda_runtime.h>
#include <cuda_bf16.h>
#include <math.h>
#include <stdint.h>

// Problem dims
#define TT   512
#define BB   64
#define INPS 256
#define HH   512

// Kernel config: per cell 16 j-pairs x 2 batch-halves = 32 CTAs; 4 cells = 128
#define NCTA 128
#define JT   32       // j rows per CTA (2 x 16-row tiles)
#define BT   32       // batch cols per CTA
#define KC   256      // K rows staged per chunk

// Smem layout
#define VROWB        80                     // staged k-row stride: 64B data + 16B pad
#define VPLANE_BYTES (KC * VROWB)           // 20480
#define VBUF_BYTES   (2 * VPLANE_BYTES)     // 40960 (hi+lo planes)
#define RS           36                     // reduction row stride (floats)
#define RED_BYTES    (8 * JT * RS * 4)      // 36864
#define SMEM_TOTAL   (2 * VBUF_BYTES + RED_BYTES)   // 118784

// ---------------- device scratch ---------------------------------------------
// Weights pre-split + pre-tiled for ldmatrix: [cell][jtile16][kc][hl][tile*64+row*8+col]
__device__ __align__(256) uint16_t g_WA[4][32][64][2][256];
__device__ __align__(256) float    g_bias[4][HH];
__device__ __align__(256) uint16_t g_x2[2][TT][INPS][BB];   // x bf16 hi/lo planes [p][t][i][b]
__device__ __align__(256) uint16_t g_h2[4][2][2][HH][BB];   // state [cell][parity][plane][j][b]
__device__ unsigned g_bar;

struct Params { const float* p[20]; };

// ---------------- helpers -----------------------------------------------------
__device__ __forceinline__ uint32_t s2u(const void* p) {
    uint32_t a;
    asm("{ .reg .u64 t; cvta.to.shared.u64 t, %1; cvt.u32.u64 %0, t; }"
        : "=r"(a) : "l"(p));
    return a;
}

__device__ __forceinline__ void ldsm_x4(uint32_t& r0, uint32_t& r1,
                                        uint32_t& r2, uint32_t& r3, uint32_t addr) {
    asm volatile("ldmatrix.sync.aligned.m8n8.x4.shared.b16 {%0,%1,%2,%3}, [%4];"
                 : "=r"(r0), "=r"(r1), "=r"(r2), "=r"(r3) : "r"(addr));
}

__device__ __forceinline__ void ldsm_x4t(uint32_t& r0, uint32_t& r1,
                                         uint32_t& r2, uint32_t& r3, uint32_t addr) {
    asm volatile("ldmatrix.sync.aligned.m8n8.x4.trans.shared.b16 {%0,%1,%2,%3}, [%4];"
                 : "=r"(r0), "=r"(r1), "=r"(r2), "=r"(r3) : "r"(addr));
}

__device__ __forceinline__ void mma_bf16(float* c,
                                         uint32_t a0, uint32_t a1, uint32_t a2, uint32_t a3,
                                         uint32_t b0, uint32_t b1) {
    asm volatile("mma.sync.aligned.m16n8k16.row.col.f32.bf16.bf16.f32 "
                 "{%0,%1,%2,%3}, {%4,%5,%6,%7}, {%8,%9}, {%0,%1,%2,%3};"
                 : "+f"(c[0]), "+f"(c[1]), "+f"(c[2]), "+f"(c[3])
                 : "r"(a0), "r"(a1), "r"(a2), "r"(a3), "r"(b0), "r"(b1));
}

__device__ __forceinline__ void cp_async16(uint32_t dst, const void* src) {
    asm volatile("cp.async.cg.shared.global [%0], [%1], 16;" :: "r"(dst), "l"(src));
}
__device__ __forceinline__ void cp_commit() { asm volatile("cp.async.commit_group;"); }
__device__ __forceinline__ void cp_wait0()  { asm volatile("cp.async.wait_group 0;" ::: "memory"); }

__device__ __forceinline__ uint32_t pack_split(float x, float y, uint32_t& lopack) {
    __nv_bfloat16 hx = __float2bfloat16(x), hy = __float2bfloat16(y);
    __nv_bfloat16 lx = __float2bfloat16(x - __bfloat162float(hx));
    __nv_bfloat16 ly = __float2bfloat16(y - __bfloat162float(hy));
    lopack = (uint32_t)__bfloat16_as_ushort(lx) | ((uint32_t)__bfloat16_as_ushort(ly) << 16);
    return (uint32_t)__bfloat16_as_ushort(hx) | ((uint32_t)__bfloat16_as_ushort(hy) << 16);
}

// ---------------- init: zero states + reset barrier --------------------------
__global__ void init_kernel() {
    int idx = blockIdx.x * blockDim.x + threadIdx.x;
    int stride = gridDim.x * blockDim.x;
    uint32_t* h = (uint32_t*)&g_h2[0][0][0][0][0];
    const int n = (int)(sizeof(g_h2) / 4);
    for (int i = idx; i < n; i += stride) h[i] = 0u;
    if (idx == 0) g_bar = 0u;
}

// ---------------- prep: split + tile weights, combine biases ------------------
__device__ __forceinline__ void put_w(int c, int j, int k, float w) {
    int jt = j >> 4, jl = j & 15, kc = k >> 4, kk = k & 15;
    int t = (jl >> 3) | ((kk >> 3) << 1);
    int off = t * 64 + (jl & 7) * 8 + (kk & 7);
    __nv_bfloat16 hi = __float2bfloat16(w);
    __nv_bfloat16 lo = __float2bfloat16(w - __bfloat162float(hi));
    g_WA[c][jt][kc][0][off] = __bfloat16_as_ushort(hi);
    g_WA[c][jt][kc][1][off] = __bfloat16_as_ushort(lo);
}

__global__ void prep_kernel(Params P) {
    int idx = blockIdx.x * blockDim.x + threadIdx.x;
    int stride = gridDim.x * blockDim.x;

    for (int i = idx; i < HH * INPS; i += stride) {
        int j = i / INPS, k = i - j * INPS;
        put_w(0, j, k, P.p[1][i]);
    }
    for (int i = idx; i < HH * HH; i += stride) {
        int j = i / HH, k = i - j * HH;
        put_w(0, j, INPS + k, P.p[3][i]);
    }
    const int ihI[3] = {5, 10, 15};
    const int mI[3]  = {6, 11, 16};
    const int hhI[3] = {8, 13, 18};
    for (int c = 0; c < 3; ++c) {
        const float* wih = P.p[ihI[c]];
        const float* msk = P.p[mI[c]];
        const float* whh = P.p[hhI[c]];
        for (int i = idx; i < HH * HH; i += stride) {
            int j = i / HH, k = i - j * HH;
            put_w(c + 1, j, k, wih[i] * msk[i]);
            put_w(c + 1, j, HH + k, whh[i]);
        }
    }
    const int bihI[4] = {2, 7, 12, 17};
    const int bhhI[4] = {4, 9, 14, 19};
    for (int i = idx; i < 4 * HH; i += stride) {
        int c = i / HH, j = i - c * HH;
        g_bias[c][j] = P.p[bihI[c]][j] + P.p[bhhI[c]][j];
    }
}

// ---------------- x convert: [t][b][i] fp32 -> hi/lo planes [p][t][i][b] -----
__global__ void xconv_kernel(const float* __restrict__ x) {
    int idx = blockIdx.x * blockDim.x + threadIdx.x;
    int stride = gridDim.x * blockDim.x;
    const int n = TT * INPS * BB;
    for (int e = idx; e < n; e += stride) {
        int t = e / (INPS * BB);
        int r = e - t * (INPS * BB);
        int i = r / BB, b = r - i * BB;
        float f = x[(t * BB + b) * INPS + i];
        __nv_bfloat16 hi = __float2bfloat16(f);
        __nv_bfloat16 lo = __float2bfloat16(f - __bfloat162float(hi));
        g_x2[0][t][i][b] = __bfloat16_as_ushort(hi);
        g_x2[1][t][i][b] = __bfloat16_as_ushort(lo);
    }
}

// ---------------- chunk staging via cp.async (batch slice of 32) -------------
__device__ __forceinline__ void issue_chunk(uint32_t vdst, int cell, int c, int t,
                                            int par, int srccell, int b0c, int tid) {
#pragma unroll
    for (int p = 0; p < 2; ++p) {
        const uint16_t* s;
        if (cell == 0)
            s = (c == 0) ? &g_x2[p][t][0][b0c]
                         : &g_h2[0][par][p][(c - 1) * KC][b0c];
        else
            s = (c < 2) ? &g_h2[srccell][par][p][c * KC][b0c]
                        : &g_h2[cell][par][p][(c - 2) * KC][b0c];
        const char* sb = (const char*)s;
        const uint32_t d = vdst + p * VPLANE_BYTES;
#pragma unroll
        for (int i = 0; i < 4; ++i) {
            const int e = i * 256 + tid;        // 0..1023: row = e>>2, seg = e&3
            cp_async16(d + (uint32_t)(e >> 2) * (uint32_t)VROWB + (uint32_t)(e & 3) * 16u,
                       sb + (size_t)(e >> 2) * (BB * 2) + (size_t)(e & 3) * 16);
        }
    }
}

// ---------------- persistent pipelined recurrence (2D split + K-split warps) --
// bid: cell = bid>>5; sub = bid&31; jpair = sub>>1 (j0 = jpair*32); btile = sub&1
// (b0c = btile*32). 8 warps K-split; A-frags (hi+lo, both j-tiles) persistent
// in 128 registers/thread. Cross-warp K-reduction through smem per step.
__global__ void __launch_bounds__(256, 1)
rec_kernel(float* __restrict__ dout) {
    extern __shared__ char smem[];
    const uint32_t smem_u = s2u(smem);
    const uint32_t vsm_u  = smem_u;
    float* redf = (float*)(smem + 2 * VBUF_BYTES);

    const int cell  = blockIdx.x >> 5;
    const int sub   = blockIdx.x & 31;
    const int jpair = sub >> 1;
    const int btile = sub & 1;
    const int j0    = jpair * JT;
    const int b0c   = btile * BT;
    const int tid   = threadIdx.x;
    const int w     = tid >> 5;
    const int lane  = tid & 31;
    const int g     = lane >> 2;
    const int tig   = lane & 3;

    const int Ktot   = (cell == 0) ? (INPS + HH) : (2 * HH);
    const int nchunk = Ktot / KC;          // 3 or 4

    // ---- load persistent A-fragments (hi+lo, 2 j-tiles) into registers ----
    // A layout: [slot(kcg local) 0..7][jt 0..1][pl 0..1][reg 0..3] -> 128 regs
    uint32_t A[128];
    {
        const uint32_t a_off = ((uint32_t)(lane >> 3) << 7) + ((uint32_t)(lane & 7) << 4);
#pragma unroll
        for (int jt = 0; jt < 2; ++jt) {
            const int4* srcw = (const int4*)&g_WA[cell][jpair * 2 + jt][0][0][0];
            int4* dstw = (int4*)smem;
            const int n4 = (Ktot / 16) * 1024 / 16;
            for (int i = tid; i < n4; i += 256) dstw[i] = srcw[i];
            __syncthreads();
#pragma unroll
            for (int c = 0; c < 4; ++c) {
                if (c < nchunk) {
#pragma unroll
                    for (int i = 0; i < 2; ++i) {
                        const int kcg = c * 16 + w * 2 + i;
                        const uint32_t aw = smem_u + (uint32_t)kcg * 1024u + a_off;
                        const int ai = ((c * 2 + i) * 2 + jt) * 8;
                        ldsm_x4(A[ai + 0], A[ai + 1], A[ai + 2], A[ai + 3], aw);
                        ldsm_x4(A[ai + 4], A[ai + 5], A[ai + 6], A[ai + 7], aw + 512u);
                    }
                }
            }
            __syncthreads();
        }
    }

    const int jj  = tid >> 3;              // 0..31 epilogue j ownership
    const int b0e = (tid & 7) * 4;         // 0..28 epilogue b ownership
    const float bias_j = g_bias[cell][j0 + jj];

    // per-lane invariant part of B ldsm address
    const uint32_t b_lane = (uint32_t)(lane & 15) * (uint32_t)VROWB
                          + ((uint32_t)(lane >> 4) << 4);

    const int delay   = (cell == 0) ? 0 : ((cell == 2) ? 2 : 1);
    const int srccell = (cell == 2) ? 1 : 0;
    unsigned bar_target = 0;

    for (int s = 0; s < TT + 2; ++s) {
        const int t = s - delay;
        const bool active = (t >= 0) && (t < TT);
        if (active) {
            const int par = s & 1;

            float acc[2][4][4];            // [jt][n8-tile][4]
#pragma unroll
            for (int a = 0; a < 2; ++a)
#pragma unroll
                for (int q = 0; q < 4; ++q) {
                    acc[a][q][0] = 0.f; acc[a][q][1] = 0.f;
                    acc[a][q][2] = 0.f; acc[a][q][3] = 0.f;
                }

            issue_chunk(vsm_u, cell, 0, t, par, srccell, b0c, tid);
            cp_commit();

            int buf = 0;
#pragma unroll
            for (int c = 0; c < 4; ++c) {
                if (c < nchunk) {
                    cp_wait0();
                    __syncthreads();
                    if (c + 1 < nchunk) {
                        issue_chunk(vsm_u + (buf ^ 1) * VBUF_BYTES,
                                    cell, c + 1, t, par, srccell, b0c, tid);
                        cp_commit();
                    }
                    const uint32_t vb = vsm_u + buf * VBUF_BYTES + b_lane;
#pragma unroll
                    for (int i = 0; i < 2; ++i) {
                        const uint32_t kb = vb + (uint32_t)((w * 2 + i) * 16) * (uint32_t)VROWB;
                        uint32_t bh[8], bl[8];   // [bt2*4 + (n8half*2 + r)]
                        ldsm_x4t(bh[0], bh[1], bh[2], bh[3], kb);
                        ldsm_x4t(bh[4], bh[5], bh[6], bh[7], kb + 32u);
                        ldsm_x4t(bl[0], bl[1], bl[2], bl[3], kb + VPLANE_BYTES);
                        ldsm_x4t(bl[4], bl[5], bl[6], bl[7], kb + VPLANE_BYTES + 32u);
                        const int slot = c * 2 + i;
#pragma unroll
                        for (int jt = 0; jt < 2; ++jt) {
                            const uint32_t* Ah = &A[(slot * 2 + jt) * 8];
                            const uint32_t* Al = Ah + 4;
#pragma unroll
                            for (int q = 0; q < 4; ++q) {
                                const uint32_t q0 = bh[(q >> 1) * 4 + (q & 1) * 2];
                                const uint32_t q1 = bh[(q >> 1) * 4 + (q & 1) * 2 + 1];
                                const uint32_t l0 = bl[(q >> 1) * 4 + (q & 1) * 2];
                                const uint32_t l1 = bl[(q >> 1) * 4 + (q & 1) * 2 + 1];
                                mma_bf16(acc[jt][q], Ah[0], Ah[1], Ah[2], Ah[3], q0, q1);
                                mma_bf16(acc[jt][q], Ah[0], Ah[1], Ah[2], Ah[3], l0, l1);
                                mma_bf16(acc[jt][q], Al[0], Al[1], Al[2], Al[3], q0, q1);
                            }
                        }
                    }
                    buf ^= 1;
                }
            }

            // ---- cross-warp K reduction ----
            {
                float* rw = redf + w * (JT * RS);
#pragma unroll
                for (int jt = 0; jt < 2; ++jt)
#pragma unroll
                    for (int q = 0; q < 4; ++q) {
                        const int b = q * 8 + tig * 2;
                        *(float2*)&rw[(jt * 16 + g) * RS + b] =
                            make_float2(acc[jt][q][0], acc[jt][q][1]);
                        *(float2*)&rw[(jt * 16 + g + 8) * RS + b] =
                            make_float2(acc[jt][q][2], acc[jt][q][3]);
                    }
            }
            __syncthreads();

            float4 sum = make_float4(bias_j, bias_j, bias_j, bias_j);
#pragma unroll
            for (int ww = 0; ww < 8; ++ww) {
                float4 v = *(const float4*)&redf[ww * (JT * RS) + jj * RS + b0e];
                sum.x += v.x; sum.y += v.y; sum.z += v.z; sum.w += v.w;
            }
            const float o0 = tanhf(sum.x), o1 = tanhf(sum.y);
            const float o2 = tanhf(sum.z), o3 = tanhf(sum.w);

            const int np = (s + 1) & 1;
            const int jg = j0 + jj;
            const int bg = b0c + b0e;
            uint32_t lo0, lo1;
            const uint32_t hi0 = pack_split(o0, o1, lo0);
            const uint32_t hi1 = pack_split(o2, o3, lo1);
            *(uint2*)&g_h2[cell][np][0][jg][bg] = make_uint2(hi0, hi1);
            *(uint2*)&g_h2[cell][np][1][jg][bg] = make_uint2(lo0, lo1);

            if (cell == 2 && t == TT - 1) {
                const uint16_t* shp = &g_h2[3][par][0][jg][bg];
                const uint16_t* slp = &g_h2[3][par][1][jg][bg];
#pragma unroll
                for (int q = 0; q < 4; ++q) {
                    float skip = __bfloat162float(__ushort_as_bfloat16(__ldcg(&shp[q])))
                               + __bfloat162float(__ushort_as_bfloat16(__ldcg(&slp[q])));
                    const float ov = (q == 0) ? o0 : (q == 1) ? o1 : (q == 2) ? o2 : o3;
                    dout[(bg + q) * HH + jg] = ov + skip;
                }
            }
        }

        // ---- grid barrier (release/acquire, all 128 CTAs) ----
        __syncthreads();
        if (tid == 0) {
            unsigned old;
            asm volatile("atom.add.release.gpu.u32 %0, [%1], 1;"
                         : "=r"(old) : "l"(&g_bar) : "memory");
            bar_target += NCTA;
            unsigned v;
            do {
                asm volatile("ld.acquire.gpu.u32 %0, [%1];"
                             : "=r"(v) : "l"(&g_bar) : "memory");
            } while (v < bar_target);
        }
        __syncthreads();
    }
}

// ---------------- launch ------------------------------------------------------
extern "C" void kernel_launch(void* const* d_in, const int* in_sizes, int n_in,
                              void* d_out, int out_size) {
    (void)in_sizes; (void)n_in; (void)out_size;

    Params P;
    for (int i = 0; i < 20; ++i) P.p[i] = (const float*)d_in[i];

    cudaFuncSetAttribute(rec_kernel,
                         cudaFuncAttributeMaxDynamicSharedMemorySize, SMEM_TOTAL);

    init_kernel<<<128, 256>>>();
    prep_kernel<<<512, 256>>>(P);
    xconv_kernel<<<512, 256>>>((const float*)d_in[0]);
    rec_kernel<<<NCTA, 256, SMEM_TOTAL>>>((float*)d_out);
}

// round 8
// speedup vs baseline: 3.2708x; 1.0552x over previous
#include <cuda_runtime.h>
#include <cuda_bf16.h>
#include <math.h>
#include <stdint.h>

// Problem dims
#define TT   512
#define BB   64
#define INPS 256
#define HH   512

// Kernel config: per cell 16 j-pairs x 2 batch-halves = 32 CTAs; 4 cells = 128
#define NCTA 128
#define JT   32       // j rows per CTA (2 x 16-row tiles)
#define BT   32       // batch cols per CTA
#define KC   256      // K rows per chunk

// Smem layout
#define VROWB        80                     // staged k-row stride: 64B data + 16B pad
#define VPLANE_BYTES (KC * VROWB)           // 20480
#define VBUF_BYTES   (2 * VPLANE_BYTES)     // 40960 (hi+lo planes)
#define RS           36                     // reduction row stride (floats)
#define RED_BYTES    (8 * JT * RS * 4)      // 36864
#define SMEM_TOTAL   (4 * VBUF_BYTES + RED_BYTES)   // 200704

// ---------------- device scratch ---------------------------------------------
__device__ __align__(256) uint16_t g_WA[4][32][64][2][256];
__device__ __align__(256) float    g_bias[4][HH];
__device__ __align__(256) uint16_t g_x2[2][TT][INPS][BB];   // x bf16 hi/lo planes [p][t][i][b]
__device__ __align__(256) uint16_t g_h2[4][2][2][HH][BB];   // state [cell][parity][plane][j][b]
__device__ __align__(128) unsigned g_barx[2][32];           // per-btile barrier counters

struct Params { const float* p[20]; };

// ---------------- helpers -----------------------------------------------------
__device__ __forceinline__ uint32_t s2u(const void* p) {
    uint32_t a;
    asm("{ .reg .u64 t; cvta.to.shared.u64 t, %1; cvt.u32.u64 %0, t; }"
        : "=r"(a) : "l"(p));
    return a;
}

__device__ __forceinline__ void ldsm_x4(uint32_t& r0, uint32_t& r1,
                                        uint32_t& r2, uint32_t& r3, uint32_t addr) {
    asm volatile("ldmatrix.sync.aligned.m8n8.x4.shared.b16 {%0,%1,%2,%3}, [%4];"
                 : "=r"(r0), "=r"(r1), "=r"(r2), "=r"(r3) : "r"(addr));
}

__device__ __forceinline__ void ldsm_x4t(uint32_t& r0, uint32_t& r1,
                                         uint32_t& r2, uint32_t& r3, uint32_t addr) {
    asm volatile("ldmatrix.sync.aligned.m8n8.x4.trans.shared.b16 {%0,%1,%2,%3}, [%4];"
                 : "=r"(r0), "=r"(r1), "=r"(r2), "=r"(r3) : "r"(addr));
}

__device__ __forceinline__ void mma_bf16(float* c,
                                         uint32_t a0, uint32_t a1, uint32_t a2, uint32_t a3,
                                         uint32_t b0, uint32_t b1) {
    asm volatile("mma.sync.aligned.m16n8k16.row.col.f32.bf16.bf16.f32 "
                 "{%0,%1,%2,%3}, {%4,%5,%6,%7}, {%8,%9}, {%0,%1,%2,%3};"
                 : "+f"(c[0]), "+f"(c[1]), "+f"(c[2]), "+f"(c[3])
                 : "r"(a0), "r"(a1), "r"(a2), "r"(a3), "r"(b0), "r"(b1));
}

__device__ __forceinline__ void cp_async16(uint32_t dst, const void* src) {
    asm volatile("cp.async.cg.shared.global [%0], [%1], 16;" :: "r"(dst), "l"(src));
}
__device__ __forceinline__ void cp_commit() { asm volatile("cp.async.commit_group;"); }
__device__ __forceinline__ void cp_wait_n(int n) {
    switch (n) {
    case 0: asm volatile("cp.async.wait_group 0;" ::: "memory"); break;
    case 1: asm volatile("cp.async.wait_group 1;" ::: "memory"); break;
    case 2: asm volatile("cp.async.wait_group 2;" ::: "memory"); break;
    default: asm volatile("cp.async.wait_group 3;" ::: "memory"); break;
    }
}

__device__ __forceinline__ uint32_t pack_split(float x, float y, uint32_t& lopack) {
    __nv_bfloat16 hx = __float2bfloat16(x), hy = __float2bfloat16(y);
    __nv_bfloat16 lx = __float2bfloat16(x - __bfloat162float(hx));
    __nv_bfloat16 ly = __float2bfloat16(y - __bfloat162float(hy));
    lopack = (uint32_t)__bfloat16_as_ushort(lx) | ((uint32_t)__bfloat16_as_ushort(ly) << 16);
    return (uint32_t)__bfloat16_as_ushort(hx) | ((uint32_t)__bfloat16_as_ushort(hy) << 16);
}

// ---------------- init: zero states + reset barriers --------------------------
__global__ void init_kernel() {
    int idx = blockIdx.x * blockDim.x + threadIdx.x;
    int stride = gridDim.x * blockDim.x;
    uint32_t* h = (uint32_t*)&g_h2[0][0][0][0][0];
    const int n = (int)(sizeof(g_h2) / 4);
    for (int i = idx; i < n; i += stride) h[i] = 0u;
    if (idx < 64) ((unsigned*)g_barx)[idx] = 0u;
}

// ---------------- prep: split + tile weights, combine biases ------------------
__device__ __forceinline__ void put_w(int c, int j, int k, float w) {
    int jt = j >> 4, jl = j & 15, kc = k >> 4, kk = k & 15;
    int t = (jl >> 3) | ((kk >> 3) << 1);
    int off = t * 64 + (jl & 7) * 8 + (kk & 7);
    __nv_bfloat16 hi = __float2bfloat16(w);
    __nv_bfloat16 lo = __float2bfloat16(w - __bfloat162float(hi));
    g_WA[c][jt][kc][0][off] = __bfloat16_as_ushort(hi);
    g_WA[c][jt][kc][1][off] = __bfloat16_as_ushort(lo);
}

__global__ void prep_kernel(Params P) {
    int idx = blockIdx.x * blockDim.x + threadIdx.x;
    int stride = gridDim.x * blockDim.x;

    for (int i = idx; i < HH * INPS; i += stride) {
        int j = i / INPS, k = i - j * INPS;
        put_w(0, j, k, P.p[1][i]);
    }
    for (int i = idx; i < HH * HH; i += stride) {
        int j = i / HH, k = i - j * HH;
        put_w(0, j, INPS + k, P.p[3][i]);
    }
    const int ihI[3] = {5, 10, 15};
    const int mI[3]  = {6, 11, 16};
    const int hhI[3] = {8, 13, 18};
    for (int c = 0; c < 3; ++c) {
        const float* wih = P.p[ihI[c]];
        const float* msk = P.p[mI[c]];
        const float* whh = P.p[hhI[c]];
        for (int i = idx; i < HH * HH; i += stride) {
            int j = i / HH, k = i - j * HH;
            put_w(c + 1, j, k, wih[i] * msk[i]);
            put_w(c + 1, j, HH + k, whh[i]);
        }
    }
    const int bihI[4] = {2, 7, 12, 17};
    const int bhhI[4] = {4, 9, 14, 19};
    for (int i = idx; i < 4 * HH; i += stride) {
        int c = i / HH, j = i - c * HH;
        g_bias[c][j] = P.p[bihI[c]][j] + P.p[bhhI[c]][j];
    }
}

// ---------------- x convert: [t][b][i] fp32 -> hi/lo planes [p][t][i][b] -----
__global__ void xconv_kernel(const float* __restrict__ x) {
    int idx = blockIdx.x * blockDim.x + threadIdx.x;
    int stride = gridDim.x * blockDim.x;
    const int n = TT * INPS * BB;
    for (int e = idx; e < n; e += stride) {
        int t = e / (INPS * BB);
        int r = e - t * (INPS * BB);
        int i = r / BB, b = r - i * BB;
        float f = x[(t * BB + b) * INPS + i];
        __nv_bfloat16 hi = __float2bfloat16(f);
        __nv_bfloat16 lo = __float2bfloat16(f - __bfloat162float(hi));
        g_x2[0][t][i][b] = __bfloat16_as_ushort(hi);
        g_x2[1][t][i][b] = __bfloat16_as_ushort(lo);
    }
}

// ---------------- chunk staging via cp.async (batch slice of 32) -------------
__device__ __forceinline__ void issue_chunk(uint32_t vdst, int cell, int c, int t,
                                            int par, int srccell, int b0c, int tid) {
#pragma unroll
    for (int p = 0; p < 2; ++p) {
        const uint16_t* s;
        if (cell == 0)
            s = (c == 0) ? &g_x2[p][t][0][b0c]
                         : &g_h2[0][par][p][(c - 1) * KC][b0c];
        else
            s = (c < 2) ? &g_h2[srccell][par][p][c * KC][b0c]
                        : &g_h2[cell][par][p][(c - 2) * KC][b0c];
        const char* sb = (const char*)s;
        const uint32_t d = vdst + p * VPLANE_BYTES;
#pragma unroll
        for (int i = 0; i < 4; ++i) {
            const int e = i * 256 + tid;        // 0..1023: row = e>>2, seg = e&3
            cp_async16(d + (uint32_t)(e >> 2) * (uint32_t)VROWB + (uint32_t)(e & 3) * 16u,
                       sb + (size_t)(e >> 2) * (BB * 2) + (size_t)(e & 3) * 16);
        }
    }
}

// ---------------- persistent pipelined recurrence -----------------------------
// bid: cell = bid>>5; sub = bid&31; jpair = sub>>1 (j0 = jpair*32); btile = sub&1.
// 8 warps K-split; A-frags persistent in 128 regs. All chunks prefetched at
// step start (4 commit groups, cascaded wait_group). Per-btile grid barrier.
__global__ void __launch_bounds__(256, 1)
rec_kernel(float* __restrict__ dout) {
    extern __shared__ char smem[];
    const uint32_t smem_u = s2u(smem);
    const uint32_t vsm_u  = smem_u;
    float* redf = (float*)(smem + 4 * VBUF_BYTES);

    const int cell  = blockIdx.x >> 5;
    const int sub   = blockIdx.x & 31;
    const int jpair = sub >> 1;
    const int btile = sub & 1;
    const int j0    = jpair * JT;
    const int b0c   = btile * BT;
    const int tid   = threadIdx.x;
    const int w     = tid >> 5;
    const int lane  = tid & 31;
    const int g     = lane >> 2;
    const int tig   = lane & 3;

    const int Ktot   = (cell == 0) ? (INPS + HH) : (2 * HH);
    const int nchunk = Ktot / KC;          // 3 or 4

    // ---- load persistent A-fragments (hi+lo, 2 j-tiles) into registers ----
    uint32_t A[128];
    {
        const uint32_t a_off = ((uint32_t)(lane >> 3) << 7) + ((uint32_t)(lane & 7) << 4);
#pragma unroll
        for (int jt = 0; jt < 2; ++jt) {
            const int4* srcw = (const int4*)&g_WA[cell][jpair * 2 + jt][0][0][0];
            int4* dstw = (int4*)smem;
            const int n4 = (Ktot / 16) * 1024 / 16;
            for (int i = tid; i < n4; i += 256) dstw[i] = srcw[i];
            __syncthreads();
#pragma unroll
            for (int c = 0; c < 4; ++c) {
                if (c < nchunk) {
#pragma unroll
                    for (int i = 0; i < 2; ++i) {
                        const int kcg = c * 16 + w * 2 + i;
                        const uint32_t aw = smem_u + (uint32_t)kcg * 1024u + a_off;
                        const int ai = ((c * 2 + i) * 2 + jt) * 8;
                        ldsm_x4(A[ai + 0], A[ai + 1], A[ai + 2], A[ai + 3], aw);
                        ldsm_x4(A[ai + 4], A[ai + 5], A[ai + 6], A[ai + 7], aw + 512u);
                    }
                }
            }
            __syncthreads();
        }
    }

    const int jj  = tid >> 3;              // 0..31 epilogue j ownership
    const int b0e = (tid & 7) * 4;         // 0..28 epilogue b ownership
    const float bias_j = g_bias[cell][j0 + jj];

    const uint32_t b_lane = (uint32_t)(lane & 15) * (uint32_t)VROWB
                          + ((uint32_t)(lane >> 4) << 4);

    const int delay   = (cell == 0) ? 0 : ((cell == 2) ? 2 : 1);
    const int srccell = (cell == 2) ? 1 : 0;
    unsigned* barp = &g_barx[btile][0];
    unsigned bar_target = 0;

    for (int s = 0; s < TT + 2; ++s) {
        const int t = s - delay;
        const bool active = (t >= 0) && (t < TT);
        if (active) {
            const int par = s & 1;

            // ---- issue ALL chunks up front (sources are ready post-barrier) ----
            for (int c = 0; c < nchunk; ++c) {
                issue_chunk(vsm_u + c * VBUF_BYTES, cell, c, t, par, srccell, b0c, tid);
                cp_commit();
            }

            float acc[2][4][4];
#pragma unroll
            for (int a = 0; a < 2; ++a)
#pragma unroll
                for (int q = 0; q < 4; ++q) {
                    acc[a][q][0] = 0.f; acc[a][q][1] = 0.f;
                    acc[a][q][2] = 0.f; acc[a][q][3] = 0.f;
                }

            for (int c = 0; c < nchunk; ++c) {
                cp_wait_n(nchunk - 1 - c);
                __syncthreads();
                const uint32_t vb = vsm_u + c * VBUF_BYTES + b_lane;
#pragma unroll
                for (int i = 0; i < 2; ++i) {
                    const uint32_t kb = vb + (uint32_t)((w * 2 + i) * 16) * (uint32_t)VROWB;
                    uint32_t bh[8], bl[8];
                    ldsm_x4t(bh[0], bh[1], bh[2], bh[3], kb);
                    ldsm_x4t(bh[4], bh[5], bh[6], bh[7], kb + 32u);
                    ldsm_x4t(bl[0], bl[1], bl[2], bl[3], kb + VPLANE_BYTES);
                    ldsm_x4t(bl[4], bl[5], bl[6], bl[7], kb + VPLANE_BYTES + 32u);
                    const int slot = c * 2 + i;
#pragma unroll
                    for (int jt = 0; jt < 2; ++jt) {
                        const uint32_t* Ah = &A[(slot * 2 + jt) * 8];
                        const uint32_t* Al = Ah + 4;
#pragma unroll
                        for (int q = 0; q < 4; ++q) {
                            const uint32_t q0 = bh[(q >> 1) * 4 + (q & 1) * 2];
                            const uint32_t q1 = bh[(q >> 1) * 4 + (q & 1) * 2 + 1];
                            const uint32_t l0 = bl[(q >> 1) * 4 + (q & 1) * 2];
                            const uint32_t l1 = bl[(q >> 1) * 4 + (q & 1) * 2 + 1];
                            mma_bf16(acc[jt][q], Ah[0], Ah[1], Ah[2], Ah[3], q0, q1);
                            mma_bf16(acc[jt][q], Ah[0], Ah[1], Ah[2], Ah[3], l0, l1);
                            mma_bf16(acc[jt][q], Al[0], Al[1], Al[2], Al[3], q0, q1);
                        }
                    }
                }
            }

            // ---- cross-warp K reduction ----
            {
                float* rw = redf + w * (JT * RS);
#pragma unroll
                for (int jt = 0; jt < 2; ++jt)
#pragma unroll
                    for (int q = 0; q < 4; ++q) {
                        const int b = q * 8 + tig * 2;
                        *(float2*)&rw[(jt * 16 + g) * RS + b] =
                            make_float2(acc[jt][q][0], acc[jt][q][1]);
                        *(float2*)&rw[(jt * 16 + g + 8) * RS + b] =
                            make_float2(acc[jt][q][2], acc[jt][q][3]);
                    }
            }
            __syncthreads();

            float4 sum = make_float4(bias_j, bias_j, bias_j, bias_j);
#pragma unroll
            for (int ww = 0; ww < 8; ++ww) {
                float4 v = *(const float4*)&redf[ww * (JT * RS) + jj * RS + b0e];
                sum.x += v.x; sum.y += v.y; sum.z += v.z; sum.w += v.w;
            }
            const float o0 = tanhf(sum.x), o1 = tanhf(sum.y);
            const float o2 = tanhf(sum.z), o3 = tanhf(sum.w);

            const int np = (s + 1) & 1;
            const int jg = j0 + jj;
            const int bg = b0c + b0e;
            uint32_t lo0, lo1;
            const uint32_t hi0 = pack_split(o0, o1, lo0);
            const uint32_t hi1 = pack_split(o2, o3, lo1);
            *(uint2*)&g_h2[cell][np][0][jg][bg] = make_uint2(hi0, hi1);
            *(uint2*)&g_h2[cell][np][1][jg][bg] = make_uint2(lo0, lo1);

            if (cell == 2 && t == TT - 1) {
                const uint16_t* shp = &g_h2[3][par][0][jg][bg];
                const uint16_t* slp = &g_h2[3][par][1][jg][bg];
#pragma unroll
                for (int q = 0; q < 4; ++q) {
                    float skip = __bfloat162float(__ushort_as_bfloat16(__ldcg(&shp[q])))
                               + __bfloat162float(__ushort_as_bfloat16(__ldcg(&slp[q])));
                    const float ov = (q == 0) ? o0 : (q == 1) ? o1 : (q == 2) ? o2 : o3;
                    dout[(bg + q) * HH + jg] = ov + skip;
                }
            }
        }

        // ---- per-btile grid barrier (64 CTAs, release/acquire) ----
        __syncthreads();
        if (tid == 0) {
            unsigned old;
            asm volatile("atom.add.release.gpu.u32 %0, [%1], 1;"
                         : "=r"(old) : "l"(barp) : "memory");
            bar_target += NCTA / 2;
            unsigned v;
            do {
                asm volatile("ld.acquire.gpu.u32 %0, [%1];"
                             : "=r"(v) : "l"(barp) : "memory");
            } while (v < bar_target);
        }
        __syncthreads();
    }
}

// ---------------- launch ------------------------------------------------------
extern "C" void kernel_launch(void* const* d_in, const int* in_sizes, int n_in,
                              void* d_out, int out_size) {
    (void)in_sizes; (void)n_in; (void)out_size;

    Params P;
    for (int i = 0; i < 20; ++i) P.p[i] = (const float*)d_in[i];

    cudaFuncSetAttribute(rec_kernel,
                         cudaFuncAttributeMaxDynamicSharedMemorySize, SMEM_TOTAL);

    init_kernel<<<128, 256>>>();
    prep_kernel<<<512, 256>>>(P);
    xconv_kernel<<<512, 256>>>((const float*)d_in[0]);
    rec_kernel<<<NCTA, 256, SMEM_TOTAL>>>((float*)d_out);
}